// round 2
// baseline (speedup 1.0000x reference)
#include <cuda_runtime.h>
#include <cuda_bf16.h>
#include <cstdint>

// ---------------- device scratch (allocations are forbidden) ----------------
__device__ float g_target[64 * 1024];          // input @ W_q^T  (B, D)
__device__ float g_epart[8 * 64 * 1024];       // per-d-tile energy partials (8, B*S)

// ---------------- small helpers ----------------
__device__ __forceinline__ uint32_t smem_u32(const void* p) {
    uint32_t a;
    asm("{ .reg .u64 t; cvta.to.shared.u64 t, %1; cvt.u32.u64 %0, t; }" : "=r"(a) : "l"(p));
    return a;
}
__device__ __forceinline__ void cp_async16(uint32_t dst, const void* src) {
    asm volatile("cp.async.cg.shared.global [%0], [%1], 16;" :: "r"(dst), "l"(src));
}
__device__ __forceinline__ void cp_commit() { asm volatile("cp.async.commit_group;" ::: "memory"); }
template<int N> __device__ __forceinline__ void cp_wait() {
    asm volatile("cp.async.wait_group %0;" :: "n"(N) : "memory");
}
__device__ __forceinline__ uint32_t f2tf32(float f) {
    uint32_t u;
    asm("cvt.rna.tf32.f32 %0, %1;" : "=r"(u) : "f"(f));
    return u;
}
__device__ __forceinline__ float tanh_fast(float x) {
    float y;
    asm("tanh.approx.f32 %0, %1;" : "=f"(y) : "f"(x));
    return y;
}
__device__ __forceinline__ void mma16816(float* d, const uint32_t* a, const uint32_t* b) {
    asm volatile(
        "mma.sync.aligned.m16n8k8.row.col.f32.tf32.tf32.f32 "
        "{%0,%1,%2,%3}, {%4,%5,%6,%7}, {%8,%9}, {%0,%1,%2,%3};"
        : "+f"(d[0]), "+f"(d[1]), "+f"(d[2]), "+f"(d[3])
        : "r"(a[0]), "r"(a[1]), "r"(a[2]), "r"(a[3]), "r"(b[0]), "r"(b[1]));
}

// =====================================================================
// k1: target[b][d] = sum_a input[b][a] * W_q[d][a]
// grid (8 d-tiles, 8 b-groups), 256 threads
// =====================================================================
__global__ void k1_target(const float* __restrict__ inp, const float* __restrict__ Wq) {
    __shared__ float insh[8][1024];
    const int dt = blockIdx.x;     // d tile of 128
    const int bg = blockIdx.y;     // b group of 8
    const int tid = threadIdx.x;   // 256
    for (int i = tid; i < 8192; i += 256)
        insh[i >> 10][i & 1023] = inp[(bg * 8 + (i >> 10)) * 1024 + (i & 1023)];
    __syncthreads();
    const int w = tid >> 5, l = tid & 31;
    for (int j = 0; j < 16; j++) {
        const int d = dt * 128 + w * 16 + j;
        const float* wr = Wq + (size_t)d * 1024;
        float acc[8] = {0.f, 0.f, 0.f, 0.f, 0.f, 0.f, 0.f, 0.f};
        for (int a = l; a < 1024; a += 32) {
            const float wv = wr[a];
#pragma unroll
            for (int bb = 0; bb < 8; bb++) acc[bb] += wv * insh[bb][a];
        }
#pragma unroll
        for (int bb = 0; bb < 8; bb++) {
            float v = acc[bb];
#pragma unroll
            for (int off = 16; off; off >>= 1) v += __shfl_xor_sync(0xffffffffu, v, off);
            if (l == 0) g_target[(bg * 8 + bb) * 1024 + d] = v;
        }
    }
}

// =====================================================================
// k2: fused GEMM (tf32 mma.sync) + tanh/energy epilogue
//   CTA tile: M=128 rows (b,s) x N=128 d, K=1024 in 64 chunks of 16.
//   8 warps arranged 4(m) x 2(n); warp tile 32x64.
//   grid: x = 8 n-tiles (fast: L2 dedups the shared context A-tile),
//         y = 512 m-tiles.
// =====================================================================
__device__ __forceinline__ void k2_load_stage(
    const float* __restrict__ ctx, const float* __restrict__ Wpre,
    float (*Ash)[20], float (*Bsh)[20],
    size_t arow0, int d0, int kt, int tid)
{
    const int k0 = kt * 16;
#pragma unroll
    for (int i = 0; i < 2; i++) {
        int c = tid + i * 256;            // 0..511
        int row = c >> 2, ch = (c & 3) * 4;
        cp_async16(smem_u32(&Ash[row][ch]), ctx + (arow0 + row) * 1024 + k0 + ch);
    }
#pragma unroll
    for (int i = 0; i < 2; i++) {
        int c = tid + i * 256;
        int row = c >> 2, ch = (c & 3) * 4;
        cp_async16(smem_u32(&Bsh[row][ch]), Wpre + (size_t)(d0 + row) * 1024 + k0 + ch);
    }
    cp_commit();
}

__global__ void __launch_bounds__(256, 2) k2_gemm(
    const float* __restrict__ ctx, const float* __restrict__ Wpre,
    const float* __restrict__ bpre, const float* __restrict__ cov,
    const float* __restrict__ Wv, const float* __restrict__ Wcov,
    float* __restrict__ outPre)
{
    __shared__ float Ash[2][128][20];
    __shared__ float Bsh[2][128][20];
    __shared__ float bpre_sh[128], wv_sh[128], wcov_sh[128], tgt_sh[128];
    __shared__ float e_sh[128][2];

    const int nt = blockIdx.x;            // 0..7   (d tile)
    const int mt = blockIdx.y;            // 0..511 (row tile)
    const int tid = threadIdx.x;
    const int lane = tid & 31, warp = tid >> 5;
    const int wm = (warp & 3) * 32;       // warp m offset
    const int wn = (warp >> 2) * 64;      // warp n offset
    const size_t arow0 = (size_t)mt * 128;
    const int b = mt >> 3;                // all 128 rows share one batch index
    const int d0 = nt * 128;

    if (tid < 128) {
        bpre_sh[tid] = bpre[d0 + tid];
        wv_sh[tid]   = Wv[d0 + tid];
        wcov_sh[tid] = Wcov[d0 + tid];
        tgt_sh[tid]  = g_target[b * 1024 + d0 + tid];
    }

    float acc[2][8][4];
#pragma unroll
    for (int i = 0; i < 2; i++)
#pragma unroll
        for (int j = 0; j < 8; j++)
#pragma unroll
            for (int r = 0; r < 4; r++) acc[i][j][r] = 0.f;

    k2_load_stage(ctx, Wpre, Ash[0], Bsh[0], arow0, d0, 0, tid);

    for (int kt = 0; kt < 64; kt++) {
        const int st = kt & 1;
        if (kt + 1 < 64) {
            k2_load_stage(ctx, Wpre, Ash[st ^ 1], Bsh[st ^ 1], arow0, d0, kt + 1, tid);
            cp_wait<1>();
        } else {
            cp_wait<0>();
        }
        __syncthreads();
#pragma unroll
        for (int k8 = 0; k8 < 2; k8++) {
            uint32_t af[2][4], bf[8][2];
            const int kk = k8 * 8 + (lane & 3);
#pragma unroll
            for (int tm = 0; tm < 2; tm++) {
                const int r0 = wm + tm * 16 + (lane >> 2);
                af[tm][0] = f2tf32(Ash[st][r0][kk]);
                af[tm][1] = f2tf32(Ash[st][r0 + 8][kk]);
                af[tm][2] = f2tf32(Ash[st][r0][kk + 4]);
                af[tm][3] = f2tf32(Ash[st][r0 + 8][kk + 4]);
            }
#pragma unroll
            for (int tn = 0; tn < 8; tn++) {
                const int c0 = wn + tn * 8 + (lane >> 2);
                bf[tn][0] = f2tf32(Bsh[st][c0][kk]);
                bf[tn][1] = f2tf32(Bsh[st][c0][kk + 4]);
            }
#pragma unroll
            for (int tm = 0; tm < 2; tm++)
#pragma unroll
                for (int tn = 0; tn < 8; tn++)
                    mma16816(acc[tm][tn], af[tm], bf[tn]);
        }
        __syncthreads();
    }

    // ---------------- epilogue: bias + write precompute + tanh/energy ----------------
    float e4[2][2] = {{0.f, 0.f}, {0.f, 0.f}};
#pragma unroll
    for (int tm = 0; tm < 2; tm++) {
#pragma unroll
        for (int h = 0; h < 2; h++) {
            const int row = wm + tm * 16 + (lane >> 2) + h * 8;
            const float cv = cov[arow0 + row];
            const size_t gbase = (arow0 + row) * 1024 + d0;
#pragma unroll
            for (int tn = 0; tn < 8; tn++) {
                const int col = wn + tn * 8 + (lane & 3) * 2;
                const float v0 = acc[tm][tn][h * 2 + 0] + bpre_sh[col];
                const float v1 = acc[tm][tn][h * 2 + 1] + bpre_sh[col + 1];
                float2 pc = make_float2(v0, v1);
                *reinterpret_cast<float2*>(&outPre[gbase + col]) = pc;
                const float a0 = v0 + tgt_sh[col]     + cv * wcov_sh[col];
                const float a1 = v1 + tgt_sh[col + 1] + cv * wcov_sh[col + 1];
                e4[tm][h] += tanh_fast(a0) * wv_sh[col];
                e4[tm][h] += tanh_fast(a1) * wv_sh[col + 1];
            }
        }
    }
#pragma unroll
    for (int tm = 0; tm < 2; tm++)
#pragma unroll
        for (int h = 0; h < 2; h++) {
            float v = e4[tm][h];
            v += __shfl_xor_sync(0xffffffffu, v, 1);
            v += __shfl_xor_sync(0xffffffffu, v, 2);
            if ((lane & 3) == 0)
                e_sh[wm + tm * 16 + (lane >> 2) + h * 8][warp >> 2] = v;
        }
    __syncthreads();
    if (tid < 128)
        g_epart[(size_t)nt * 65536 + mt * 128 + tid] = e_sh[tid][0] + e_sh[tid][1];
}

// =====================================================================
// k3: energy reduce + softmax + coverage.  One block per b, 256 threads.
// =====================================================================
__global__ void k3_softmax(const float* __restrict__ cov, float* __restrict__ out) {
    __shared__ float red[32];
    const int b = blockIdx.x, tid = threadIdx.x;
    float e[4];
#pragma unroll
    for (int i = 0; i < 4; i++) {
        const int s = tid + i * 256;
        float v = 0.f;
#pragma unroll
        for (int nt = 0; nt < 8; nt++) v += g_epart[(size_t)nt * 65536 + b * 1024 + s];
        e[i] = v;
    }
    float mx = fmaxf(fmaxf(e[0], e[1]), fmaxf(e[2], e[3]));
#pragma unroll
    for (int off = 16; off; off >>= 1) mx = fmaxf(mx, __shfl_xor_sync(0xffffffffu, mx, off));
    if ((tid & 31) == 0) red[tid >> 5] = mx;
    __syncthreads();
    if (tid < 32) {
        float m = (tid < 8) ? red[tid] : -1e30f;
#pragma unroll
        for (int off = 4; off; off >>= 1) m = fmaxf(m, __shfl_xor_sync(0xffffffffu, m, off));
        red[tid] = m;
    }
    __syncthreads();
    mx = red[0];
    __syncthreads();

    float ex[4], sum = 0.f;
#pragma unroll
    for (int i = 0; i < 4; i++) { ex[i] = __expf(e[i] - mx); sum += ex[i]; }
#pragma unroll
    for (int off = 16; off; off >>= 1) sum += __shfl_xor_sync(0xffffffffu, sum, off);
    if ((tid & 31) == 0) red[tid >> 5] = sum;
    __syncthreads();
    if (tid < 32) {
        float s = (tid < 8) ? red[tid] : 0.f;
#pragma unroll
        for (int off = 4; off; off >>= 1) s += __shfl_xor_sync(0xffffffffu, s, off);
        red[tid] = s;
    }
    __syncthreads();
    const float inv = 1.f / red[0];
#pragma unroll
    for (int i = 0; i < 4; i++) {
        const int s = tid + i * 256;
        const float sc = ex[i] * inv;
        out[65536 + b * 1024 + s]  = sc;                       // score
        out[131072 + b * 1024 + s] = cov[b * 1024 + s] + sc;   // coverage_new
    }
}

// =====================================================================
// k4: weightedContext[b][a] = sum_s score[b][s] * context[b][s][a]
// grid (64 b, 8 a-chunks of 128), 128 threads
// =====================================================================
__global__ void k4_wctx(const float* __restrict__ ctx, const float* __restrict__ score,
                        float* __restrict__ out) {
    __shared__ float sc[1024];
    const int b = blockIdx.x, ac = blockIdx.y, tid = threadIdx.x;
    for (int i = tid; i < 1024; i += 128) sc[i] = score[b * 1024 + i];
    __syncthreads();
    const int a = ac * 128 + tid;
    const float* cp = ctx + (size_t)b * 1024 * 1024 + a;
    float acc0 = 0.f, acc1 = 0.f, acc2 = 0.f, acc3 = 0.f;
#pragma unroll 4
    for (int s = 0; s < 1024; s += 4) {
        acc0 += sc[s + 0] * cp[(size_t)(s + 0) * 1024];
        acc1 += sc[s + 1] * cp[(size_t)(s + 1) * 1024];
        acc2 += sc[s + 2] * cp[(size_t)(s + 2) * 1024];
        acc3 += sc[s + 3] * cp[(size_t)(s + 3) * 1024];
    }
    out[b * 1024 + a] = (acc0 + acc1) + (acc2 + acc3);
}

// =====================================================================
extern "C" void kernel_launch(void* const* d_in, const int* in_sizes, int n_in,
                              void* d_out, int out_size) {
    const float* input   = (const float*)d_in[0];  // (64, 1024)
    const float* context = (const float*)d_in[1];  // (64, 1024, 1024)
    const float* cov     = (const float*)d_in[2];  // (64, 1024)
    const float* Wpre    = (const float*)d_in[3];  // (1024, 1024)
    const float* bpre    = (const float*)d_in[4];  // (1024,)
    const float* Wq      = (const float*)d_in[5];  // (1024, 1024)
    const float* Wv      = (const float*)d_in[6];  // (1, 1024)
    const float* Wcov    = (const float*)d_in[7];  // (1024, 1)
    float* out = (float*)d_out;
    // out layout: weightedContext (65536) | score (65536) | coverage_new (65536)
    //             | precompute (67108864)

    dim3 g1(8, 8);
    k1_target<<<g1, 256>>>(input, Wq);

    dim3 g2(8, 512);
    k2_gemm<<<g2, 256>>>(context, Wpre, bpre, cov, Wv, Wcov, out + 196608);

    k3_softmax<<<64, 256>>>(cov, out);

    dim3 g4(64, 8);
    k4_wctx<<<g4, 128>>>(context, out + 65536, out);
}

// round 4
// speedup vs baseline: 1.0421x; 1.0421x over previous
#include <cuda_runtime.h>
#include <cstdint>

// ---------------- device scratch (allocations are forbidden) ----------------
__device__ float g_target[64 * 1024];          // input @ W_q^T  (B, D)
__device__ float g_epart[8 * 64 * 1024];       // per-d-tile energy partials (8, B*S)

// ---------------- helpers ----------------
__device__ __forceinline__ uint32_t smem_u32(const void* p) {
    uint32_t a;
    asm("{ .reg .u64 t; cvta.to.shared.u64 t, %1; cvt.u32.u64 %0, t; }" : "=r"(a) : "l"(p));
    return a;
}
__device__ __forceinline__ void cp_async16(uint32_t dst, const void* src) {
    asm volatile("cp.async.cg.shared.global [%0], [%1], 16;" :: "r"(dst), "l"(src));
}
__device__ __forceinline__ void cp_commit() { asm volatile("cp.async.commit_group;" ::: "memory"); }
template<int N> __device__ __forceinline__ void cp_wait() {
    asm volatile("cp.async.wait_group %0;" :: "n"(N) : "memory");
}
__device__ __forceinline__ uint32_t f2tf32(uint32_t f) {
    uint32_t u;
    asm("cvt.rna.tf32.f32 %0, %1;" : "=r"(u) : "r"(f));
    return u;
}
__device__ __forceinline__ float tanh_fast(float x) {
    float y;
    asm("tanh.approx.f32 %0, %1;" : "=f"(y) : "f"(x));
    return y;
}
__device__ __forceinline__ void ldsm4(uint32_t& r0, uint32_t& r1, uint32_t& r2,
                                      uint32_t& r3, uint32_t addr) {
    asm volatile("ldmatrix.sync.aligned.m8n8.x4.shared.b16 {%0,%1,%2,%3}, [%4];"
                 : "=r"(r0), "=r"(r1), "=r"(r2), "=r"(r3) : "r"(addr));
}
__device__ __forceinline__ void mma16816(float* d, const uint32_t* a, const uint32_t* b) {
    asm volatile(
        "mma.sync.aligned.m16n8k8.row.col.f32.tf32.tf32.f32 "
        "{%0,%1,%2,%3}, {%4,%5,%6,%7}, {%8,%9}, {%0,%1,%2,%3};"
        : "+f"(d[0]), "+f"(d[1]), "+f"(d[2]), "+f"(d[3])
        : "r"(a[0]), "r"(a[1]), "r"(a[2]), "r"(a[3]), "r"(b[0]), "r"(b[1]));
}

// =====================================================================
// k1: target[b][d] = sum_a input[b][a] * W_q[d][a]
// =====================================================================
__global__ void k1_target(const float* __restrict__ inp, const float* __restrict__ Wq) {
    __shared__ float insh[8][1024];
    const int dt = blockIdx.x, bg = blockIdx.y, tid = threadIdx.x;
    for (int i = tid; i < 8192; i += 256)
        insh[i >> 10][i & 1023] = inp[(bg * 8 + (i >> 10)) * 1024 + (i & 1023)];
    __syncthreads();
    const int w = tid >> 5, l = tid & 31;
    for (int j = 0; j < 16; j++) {
        const int d = dt * 128 + w * 16 + j;
        const float* wr = Wq + (size_t)d * 1024;
        float acc[8] = {0.f, 0.f, 0.f, 0.f, 0.f, 0.f, 0.f, 0.f};
        for (int a = l; a < 1024; a += 32) {
            const float wv = wr[a];
#pragma unroll
            for (int bb = 0; bb < 8; bb++) acc[bb] += wv * insh[bb][a];
        }
#pragma unroll
        for (int bb = 0; bb < 8; bb++) {
            float v = acc[bb];
#pragma unroll
            for (int off = 16; off; off >>= 1) v += __shfl_xor_sync(0xffffffffu, v, off);
            if (l == 0) g_target[(bg * 8 + bb) * 1024 + d] = v;
        }
    }
}

// =====================================================================
// k2: tf32 mma.sync GEMM + fused tanh/energy epilogue
//   CTA tile 128(M) x 128(N), K=1024 in 64 chunks of 16, 3-stage cp.async.
//   4 warps, each 64x64 (2x2 arrangement). ldmatrix.x4 fragment loads.
//   smem per stage: A 128x16 f32 (8KB, swizzled) + B 128x16 f32 (8KB).
// =====================================================================
constexpr int K2_STAGE   = 16384;
constexpr int K2_VEC_OFF = 49152;   // 4 x 128 floats = 2KB
constexpr int K2_ESH_OFF = 51200;   // 128 x 2 floats = 1KB
constexpr int K2_SMEM    = 52224;

__device__ __forceinline__ uint32_t swz_off(int r, int c) {
    return (uint32_t)(r * 64 + ((c ^ ((r >> 1) & 3)) << 4));
}

__device__ __forceinline__ void k2_load(
    const float* __restrict__ ctx, const float* __restrict__ Wpre,
    uint32_t sb, int st, size_t row0, int d0, int kt, int tid)
{
    const int k0 = kt * 16;
    const uint32_t abase = sb + st * K2_STAGE;
    const uint32_t bbase = abase + 8192;
#pragma unroll
    for (int i = 0; i < 4; i++) {
        const int id = tid + i * 128;            // 0..511
        const int r = id >> 2, c = id & 3;
        cp_async16(abase + swz_off(r, c), ctx + (row0 + r) * 1024 + k0 + c * 4);
    }
#pragma unroll
    for (int i = 0; i < 4; i++) {
        const int id = tid + i * 128;
        const int r = id >> 2, c = id & 3;
        cp_async16(bbase + swz_off(r, c), Wpre + (size_t)(d0 + r) * 1024 + k0 + c * 4);
    }
    cp_commit();
}

__global__ void __launch_bounds__(128, 2) k2_gemm(
    const float* __restrict__ ctx, const float* __restrict__ Wpre,
    const float* __restrict__ bpre, const float* __restrict__ cov,
    const float* __restrict__ Wv, const float* __restrict__ Wcov,
    float* __restrict__ outPre)
{
    extern __shared__ char smem[];
    const uint32_t sb = smem_u32(smem);
    float* vecs = (float*)(smem + K2_VEC_OFF);
    float (*e_sh)[2] = (float (*)[2])(smem + K2_ESH_OFF);

    const int nt = blockIdx.x;                 // 0..7  (128-wide d tile)
    const int mt = blockIdx.y;                 // 0..511 (128-row tile)
    const int tid = threadIdx.x;
    const int lane = tid & 31, warp = tid >> 5;
    const int wm = (warp & 1) * 64, wn = (warp >> 1) * 64;
    const int d0 = nt * 128;
    const size_t row0 = (size_t)mt * 128;
    const int b = mt >> 3;

    vecs[tid]       = bpre[d0 + tid];
    vecs[128 + tid] = g_target[b * 1024 + d0 + tid];
    vecs[256 + tid] = Wv[d0 + tid];
    vecs[384 + tid] = Wcov[d0 + tid];

    // per-lane ldmatrix row bases
    const int idx  = lane & 7;
    const int qrow = (lane >> 3) & 1;          // row half of the 16-row tile
    const int qk   = lane >> 4;                // k half (granule +0 / +1)
    uint32_t offA[4], offB[4];
    int swzA[4], swzB[4];
#pragma unroll
    for (int t = 0; t < 4; t++) {
        const int rA = wm + t * 16 + qrow * 8 + idx;
        offA[t] = (uint32_t)(rA * 64);
        swzA[t] = (rA >> 1) & 3;
        const int rB = wn + t * 16 + qrow * 8 + idx;
        offB[t] = (uint32_t)(8192 + rB * 64);
        swzB[t] = (rB >> 1) & 3;
    }

    float acc[4][8][4];
#pragma unroll
    for (int i = 0; i < 4; i++)
#pragma unroll
        for (int j = 0; j < 8; j++)
#pragma unroll
            for (int r = 0; r < 4; r++) acc[i][j][r] = 0.f;

    k2_load(ctx, Wpre, sb, 0, row0, d0, 0, tid);
    k2_load(ctx, Wpre, sb, 1, row0, d0, 1, tid);
    k2_load(ctx, Wpre, sb, 2, row0, d0, 2, tid);

    int st = 0;
    for (int kt = 0; kt < 64; kt++) {
        if (kt < 62) cp_wait<2>();
        else if (kt == 62) cp_wait<1>();
        else cp_wait<0>();
        __syncthreads();

        const uint32_t stb = sb + st * K2_STAGE;
#pragma unroll
        for (int s = 0; s < 2; s++) {
            uint32_t a[4][4], bq[4][4];
#pragma unroll
            for (int tm = 0; tm < 4; tm++)
                ldsm4(a[tm][0], a[tm][1], a[tm][2], a[tm][3],
                      stb + offA[tm] + (uint32_t)(((2 * s + qk) ^ swzA[tm]) << 4));
#pragma unroll
            for (int tp = 0; tp < 4; tp++)
                ldsm4(bq[tp][0], bq[tp][1], bq[tp][2], bq[tp][3],
                      stb + offB[tp] + (uint32_t)(((2 * s + qk) ^ swzB[tp]) << 4));
#pragma unroll
            for (int tm = 0; tm < 4; tm++)
#pragma unroll
                for (int r = 0; r < 4; r++) a[tm][r] = f2tf32(a[tm][r]);
#pragma unroll
            for (int tp = 0; tp < 4; tp++)
#pragma unroll
                for (int r = 0; r < 4; r++) bq[tp][r] = f2tf32(bq[tp][r]);
#pragma unroll
            for (int tm = 0; tm < 4; tm++)
#pragma unroll
                for (int tn = 0; tn < 8; tn++) {
                    uint32_t bb[2] = { bq[tn >> 1][tn & 1], bq[tn >> 1][2 + (tn & 1)] };
                    mma16816(acc[tm][tn], a[tm], bb);
                }
        }
        __syncthreads();
        if (kt + 3 < 64) k2_load(ctx, Wpre, sb, st, row0, d0, kt + 3, tid);
        st = (st == 2) ? 0 : st + 1;
    }

    // ---------------- epilogue ----------------
    const int g = lane >> 2, t4 = lane & 3;
    const float* bias_sh = vecs;
    const float* tgt_sh  = vecs + 128;
    const float* wv_sh   = vecs + 256;
    const float* wcov_sh = vecs + 384;

#pragma unroll
    for (int tm = 0; tm < 4; tm++) {
#pragma unroll
        for (int h = 0; h < 2; h++) {
            const int rowL = wm + tm * 16 + h * 8 + g;
            const size_t grow = row0 + rowL;
            const float cv = cov[grow];
            float* orow = outPre + grow * 1024 + d0;
            float e = 0.f;
#pragma unroll
            for (int tn = 0; tn < 8; tn++) {
                const int colL = wn + tn * 8 + 2 * t4;
                const float v0 = acc[tm][tn][h * 2 + 0] + bias_sh[colL];
                const float v1 = acc[tm][tn][h * 2 + 1] + bias_sh[colL + 1];
                *reinterpret_cast<float2*>(orow + colL) = make_float2(v0, v1);
                e += tanh_fast(v0 + tgt_sh[colL]     + cv * wcov_sh[colL])     * wv_sh[colL];
                e += tanh_fast(v1 + tgt_sh[colL + 1] + cv * wcov_sh[colL + 1]) * wv_sh[colL + 1];
            }
            e += __shfl_xor_sync(0xffffffffu, e, 1);
            e += __shfl_xor_sync(0xffffffffu, e, 2);
            if (t4 == 0) e_sh[rowL][warp >> 1] = e;
        }
    }
    __syncthreads();
    if (tid < 128)
        g_epart[(size_t)nt * 65536 + row0 + tid] = e_sh[tid][0] + e_sh[tid][1];
}

// =====================================================================
// k3: energy reduce + softmax + coverage. One block per b, 256 threads.
// =====================================================================
__global__ void k3_softmax(const float* __restrict__ cov, float* __restrict__ out) {
    __shared__ float red[32];
    const int b = blockIdx.x, tid = threadIdx.x;
    float e[4];
#pragma unroll
    for (int i = 0; i < 4; i++) {
        const int s = tid + i * 256;
        float v = 0.f;
#pragma unroll
        for (int nt = 0; nt < 8; nt++) v += g_epart[(size_t)nt * 65536 + b * 1024 + s];
        e[i] = v;
    }
    float mx = fmaxf(fmaxf(e[0], e[1]), fmaxf(e[2], e[3]));
#pragma unroll
    for (int off = 16; off; off >>= 1) mx = fmaxf(mx, __shfl_xor_sync(0xffffffffu, mx, off));
    if ((tid & 31) == 0) red[tid >> 5] = mx;
    __syncthreads();
    if (tid < 32) {
        float m = (tid < 8) ? red[tid] : -1e30f;
#pragma unroll
        for (int off = 4; off; off >>= 1) m = fmaxf(m, __shfl_xor_sync(0xffffffffu, m, off));
        red[tid] = m;
    }
    __syncthreads();
    mx = red[0];
    __syncthreads();

    float ex[4], sum = 0.f;
#pragma unroll
    for (int i = 0; i < 4; i++) { ex[i] = __expf(e[i] - mx); sum += ex[i]; }
#pragma unroll
    for (int off = 16; off; off >>= 1) sum += __shfl_xor_sync(0xffffffffu, sum, off);
    if ((tid & 31) == 0) red[tid >> 5] = sum;
    __syncthreads();
    if (tid < 32) {
        float s = (tid < 8) ? red[tid] : 0.f;
#pragma unroll
        for (int off = 4; off; off >>= 1) s += __shfl_xor_sync(0xffffffffu, s, off);
        red[tid] = s;
    }
    __syncthreads();
    const float inv = 1.f / red[0];
#pragma unroll
    for (int i = 0; i < 4; i++) {
        const int s = tid + i * 256;
        const float sc = ex[i] * inv;
        out[65536 + b * 1024 + s]  = sc;                       // score
        out[131072 + b * 1024 + s] = cov[b * 1024 + s] + sc;   // coverage_new
    }
}

// =====================================================================
// k4: weightedContext[b][a] = sum_s score[b][s] * context[b][s][a]
// grid 128 CTAs (b, half), 128 threads; float4 columns; unroll 16
// =====================================================================
__global__ void __launch_bounds__(128) k4_wctx(
    const float* __restrict__ ctx, const float* __restrict__ score,
    float* __restrict__ out)
{
    __shared__ float sc[1024];
    const int b = blockIdx.x >> 1, half = blockIdx.x & 1, tid = threadIdx.x;
    for (int i = tid; i < 1024; i += 128) sc[i] = score[b * 1024 + i];
    __syncthreads();
    const int a4 = half * 128 + tid;                 // float4 column 0..255
    const float4* cp = (const float4*)(ctx + (size_t)b * 1048576) + a4;
    float4 acc = make_float4(0.f, 0.f, 0.f, 0.f);
    for (int s0 = 0; s0 < 1024; s0 += 16) {
        float4 v[16];
#pragma unroll
        for (int u = 0; u < 16; u++) v[u] = cp[(size_t)(s0 + u) * 256];
#pragma unroll
        for (int u = 0; u < 16; u++) {
            const float s = sc[s0 + u];
            acc.x += s * v[u].x; acc.y += s * v[u].y;
            acc.z += s * v[u].z; acc.w += s * v[u].w;
        }
    }
    ((float4*)out)[b * 256 + a4] = acc;
}

// =====================================================================
extern "C" void kernel_launch(void* const* d_in, const int* in_sizes, int n_in,
                              void* d_out, int out_size) {
    const float* input   = (const float*)d_in[0];
    const float* context = (const float*)d_in[1];
    const float* cov     = (const float*)d_in[2];
    const float* Wpre    = (const float*)d_in[3];
    const float* bpre    = (const float*)d_in[4];
    const float* Wq      = (const float*)d_in[5];
    const float* Wv      = (const float*)d_in[6];
    const float* Wcov    = (const float*)d_in[7];
    float* out = (float*)d_out;
    // layout: weightedContext (65536) | score (65536) | coverage_new (65536)
    //         | precompute (67108864)

    cudaFuncSetAttribute(k2_gemm, cudaFuncAttributeMaxDynamicSharedMemorySize, K2_SMEM);

    dim3 g1(8, 8);
    k1_target<<<g1, 256>>>(input, Wq);

    dim3 g2(8, 512);
    k2_gemm<<<g2, 128, K2_SMEM>>>(context, Wpre, bpre, cov, Wv, Wcov, out + 196608);

    k3_softmax<<<64, 256>>>(cov, out);

    k4_wctx<<<128, 128>>>(context, out + 65536, out);
}

// round 5
// speedup vs baseline: 1.2107x; 1.1618x over previous
#include <cuda_runtime.h>
#include <cuda_fp16.h>
#include <cstdint>

// ---------------- device scratch (allocations are forbidden) ----------------
__device__ float g_target[64 * 1024];          // input @ W_q^T  (B, D)
__device__ float g_epart[8 * 64 * 1024];       // per-d-tile energy partials (8, B*S)
__device__ __half g_ctx_h[64 * 1024 * 1024];   // fp16 context (128 MB)
__device__ __half g_wpre_h[1024 * 1024];       // fp16 W_pre (2 MB)

// ---------------- helpers ----------------
__device__ __forceinline__ uint32_t smem_u32(const void* p) {
    uint32_t a;
    asm("{ .reg .u64 t; cvta.to.shared.u64 t, %1; cvt.u32.u64 %0, t; }" : "=r"(a) : "l"(p));
    return a;
}
__device__ __forceinline__ void cp_async16(uint32_t dst, const void* src) {
    asm volatile("cp.async.cg.shared.global [%0], [%1], 16;" :: "r"(dst), "l"(src));
}
__device__ __forceinline__ void cp_commit() { asm volatile("cp.async.commit_group;" ::: "memory"); }
template<int N> __device__ __forceinline__ void cp_wait() {
    asm volatile("cp.async.wait_group %0;" :: "n"(N) : "memory");
}
__device__ __forceinline__ float tanh_fast(float x) {
    float y;
    asm("tanh.approx.f32 %0, %1;" : "=f"(y) : "f"(x));
    return y;
}
__device__ __forceinline__ void ldsm4(uint32_t& r0, uint32_t& r1, uint32_t& r2,
                                      uint32_t& r3, uint32_t addr) {
    asm volatile("ldmatrix.sync.aligned.m8n8.x4.shared.b16 {%0,%1,%2,%3}, [%4];"
                 : "=r"(r0), "=r"(r1), "=r"(r2), "=r"(r3) : "r"(addr));
}
__device__ __forceinline__ void mma_f16(float* d, const uint32_t* a, uint32_t b0, uint32_t b1) {
    asm volatile(
        "mma.sync.aligned.m16n8k16.row.col.f32.f16.f16.f32 "
        "{%0,%1,%2,%3}, {%4,%5,%6,%7}, {%8,%9}, {%0,%1,%2,%3};"
        : "+f"(d[0]), "+f"(d[1]), "+f"(d[2]), "+f"(d[3])
        : "r"(a[0]), "r"(a[1]), "r"(a[2]), "r"(a[3]), "r"(b0), "r"(b1));
}

// =====================================================================
// k0: f32 -> fp16 conversion (context / W_pre) into device globals
// =====================================================================
__global__ void k0_ctx(const float4* __restrict__ src) {
    uint2* dst = reinterpret_cast<uint2*>(g_ctx_h);
    const int stride = gridDim.x * blockDim.x;
    for (int i = blockIdx.x * blockDim.x + threadIdx.x; i < 16777216; i += stride) {
        float4 v = src[i];
        __half2 h0 = __float22half2_rn(make_float2(v.x, v.y));
        __half2 h1 = __float22half2_rn(make_float2(v.z, v.w));
        uint2 o;
        o.x = *reinterpret_cast<uint32_t*>(&h0);
        o.y = *reinterpret_cast<uint32_t*>(&h1);
        dst[i] = o;
    }
}
__global__ void k0_wpre(const float4* __restrict__ src) {
    uint2* dst = reinterpret_cast<uint2*>(g_wpre_h);
    const int stride = gridDim.x * blockDim.x;
    for (int i = blockIdx.x * blockDim.x + threadIdx.x; i < 262144; i += stride) {
        float4 v = src[i];
        __half2 h0 = __float22half2_rn(make_float2(v.x, v.y));
        __half2 h1 = __float22half2_rn(make_float2(v.z, v.w));
        uint2 o;
        o.x = *reinterpret_cast<uint32_t*>(&h0);
        o.y = *reinterpret_cast<uint32_t*>(&h1);
        dst[i] = o;
    }
}

// =====================================================================
// k1: target[b][d] = sum_a input[b][a] * W_q[d][a]   (fp32 exact)
// =====================================================================
__global__ void k1_target(const float* __restrict__ inp, const float* __restrict__ Wq) {
    __shared__ float insh[8][1024];
    const int dt = blockIdx.x, bg = blockIdx.y, tid = threadIdx.x;
    for (int i = tid; i < 8192; i += 256)
        insh[i >> 10][i & 1023] = inp[(bg * 8 + (i >> 10)) * 1024 + (i & 1023)];
    __syncthreads();
    const int w = tid >> 5, l = tid & 31;
    for (int j = 0; j < 16; j++) {
        const int d = dt * 128 + w * 16 + j;
        const float* wr = Wq + (size_t)d * 1024;
        float acc[8] = {0.f, 0.f, 0.f, 0.f, 0.f, 0.f, 0.f, 0.f};
        for (int a = l; a < 1024; a += 32) {
            const float wv = wr[a];
#pragma unroll
            for (int bb = 0; bb < 8; bb++) acc[bb] += wv * insh[bb][a];
        }
#pragma unroll
        for (int bb = 0; bb < 8; bb++) {
            float v = acc[bb];
#pragma unroll
            for (int off = 16; off; off >>= 1) v += __shfl_xor_sync(0xffffffffu, v, off);
            if (l == 0) g_target[(bg * 8 + bb) * 1024 + d] = v;
        }
    }
}

// =====================================================================
// k2: fp16 mma.sync m16n8k16 GEMM + fused tanh/energy epilogue
//   CTA tile 128(M) x 128(N), K=1024 in 64 chunks of 16, 3-stage cp.async.
//   4 warps, each 64x64 (2x2). Stage = A 128x16 fp16 (4KB) + B 4KB.
// =====================================================================
constexpr int K2_STAGE   = 8192;
constexpr int K2_VEC_OFF = 24576;   // 4 x 128 floats = 2KB
constexpr int K2_ESH_OFF = 26624;   // 128 x 2 floats = 1KB
constexpr int K2_SMEM    = 27648;

__device__ __forceinline__ void k2_load(uint32_t sb, int st, size_t row0, int d0,
                                        int kt, int tid) {
    const uint32_t abase = sb + st * K2_STAGE;
    const uint32_t bbase = abase + 4096;
    const __half* ap = g_ctx_h + (row0 + tid) * 1024 + kt * 16;
    const __half* bp = g_wpre_h + (size_t)(d0 + tid) * 1024 + kt * 16;
    const uint32_t swz = ((tid >> 2) & 1) << 4;      // (r>>2)&1 swizzle bit
    cp_async16(abase + tid * 32 + swz, ap);
    cp_async16(abase + tid * 32 + (swz ^ 16), ap + 8);
    cp_async16(bbase + tid * 32 + swz, bp);
    cp_async16(bbase + tid * 32 + (swz ^ 16), bp + 8);
    cp_commit();
}

__global__ void __launch_bounds__(128, 2) k2_gemm(
    const float* __restrict__ bpre, const float* __restrict__ cov,
    const float* __restrict__ Wv, const float* __restrict__ Wcov,
    float* __restrict__ outPre)
{
    extern __shared__ char smem[];
    const uint32_t sb = smem_u32(smem);
    float* vecs = (float*)(smem + K2_VEC_OFF);
    float (*e_sh)[2] = (float (*)[2])(smem + K2_ESH_OFF);

    const int nt = blockIdx.x;                 // 0..7   (128-wide d tile)
    const int mt = blockIdx.y;                 // 0..511 (128-row tile)
    const int tid = threadIdx.x;
    const int lane = tid & 31, warp = tid >> 5;
    const int wm = (warp & 1) * 64, wn = (warp >> 1) * 64;
    const int d0 = nt * 128;
    const size_t row0 = (size_t)mt * 128;
    const int b = mt >> 3;

    vecs[tid]       = bpre[d0 + tid];
    vecs[128 + tid] = g_target[b * 1024 + d0 + tid];
    vecs[256 + tid] = Wv[d0 + tid];
    vecs[384 + tid] = Wcov[d0 + tid];

    // per-lane ldmatrix addresses (constant across kt)
    const int sub = lane >> 3, idx = lane & 7;
    const int rit = (sub & 1) * 8 + idx;       // row within 16-row tile
    const int kseg = sub >> 1;                 // k half (0/1)
    uint32_t offA[4], offB[4];
#pragma unroll
    for (int t = 0; t < 4; t++) {
        const int rA = wm + t * 16 + rit;
        offA[t] = (uint32_t)(rA * 32 + ((kseg ^ ((rA >> 2) & 1)) << 4));
        const int rB = wn + t * 16 + rit;
        offB[t] = (uint32_t)(4096 + rB * 32 + ((kseg ^ ((rB >> 2) & 1)) << 4));
    }

    float acc[4][8][4];
#pragma unroll
    for (int i = 0; i < 4; i++)
#pragma unroll
        for (int j = 0; j < 8; j++)
#pragma unroll
            for (int r = 0; r < 4; r++) acc[i][j][r] = 0.f;

    k2_load(sb, 0, row0, d0, 0, tid);
    k2_load(sb, 1, row0, d0, 1, tid);
    k2_load(sb, 2, row0, d0, 2, tid);

    int st = 0;
    for (int kt = 0; kt < 64; kt++) {
        if (kt < 62) cp_wait<2>();
        else if (kt == 62) cp_wait<1>();
        else cp_wait<0>();
        __syncthreads();

        const uint32_t stb = sb + st * K2_STAGE;
        uint32_t a[4][4], bq[4][4];
#pragma unroll
        for (int tm = 0; tm < 4; tm++)
            ldsm4(a[tm][0], a[tm][1], a[tm][2], a[tm][3], stb + offA[tm]);
#pragma unroll
        for (int tp = 0; tp < 4; tp++)
            ldsm4(bq[tp][0], bq[tp][1], bq[tp][2], bq[tp][3], stb + offB[tp]);
#pragma unroll
        for (int tm = 0; tm < 4; tm++)
#pragma unroll
            for (int tn = 0; tn < 8; tn++)
                mma_f16(acc[tm][tn], a[tm],
                        bq[tn >> 1][tn & 1], bq[tn >> 1][2 + (tn & 1)]);

        __syncthreads();
        if (kt + 3 < 64) k2_load(sb, st, row0, d0, kt + 3, tid);
        st = (st == 2) ? 0 : st + 1;
    }

    // ---------------- epilogue: bias + precompute + tanh/energy ----------------
    const int g = lane >> 2, t4 = lane & 3;
    const float* bias_sh = vecs;
    const float* tgt_sh  = vecs + 128;
    const float* wv_sh   = vecs + 256;
    const float* wcov_sh = vecs + 384;

#pragma unroll
    for (int tm = 0; tm < 4; tm++) {
#pragma unroll
        for (int h = 0; h < 2; h++) {
            const int rowL = wm + tm * 16 + h * 8 + g;
            const size_t grow = row0 + rowL;
            const float cv = cov[grow];
            float* orow = outPre + grow * 1024 + d0;
            float e = 0.f;
#pragma unroll
            for (int tn = 0; tn < 8; tn++) {
                const int colL = wn + tn * 8 + 2 * t4;
                const float v0 = acc[tm][tn][h * 2 + 0] + bias_sh[colL];
                const float v1 = acc[tm][tn][h * 2 + 1] + bias_sh[colL + 1];
                *reinterpret_cast<float2*>(orow + colL) = make_float2(v0, v1);
                e += tanh_fast(v0 + tgt_sh[colL]     + cv * wcov_sh[colL])     * wv_sh[colL];
                e += tanh_fast(v1 + tgt_sh[colL + 1] + cv * wcov_sh[colL + 1]) * wv_sh[colL + 1];
            }
            e += __shfl_xor_sync(0xffffffffu, e, 1);
            e += __shfl_xor_sync(0xffffffffu, e, 2);
            if (t4 == 0) e_sh[rowL][warp >> 1] = e;
        }
    }
    __syncthreads();
    if (tid < 128)
        g_epart[(size_t)nt * 65536 + row0 + tid] = e_sh[tid][0] + e_sh[tid][1];
}

// =====================================================================
// k3: energy reduce + softmax + coverage. One block per b, 256 threads.
// =====================================================================
__global__ void k3_softmax(const float* __restrict__ cov, float* __restrict__ out) {
    __shared__ float red[32];
    const int b = blockIdx.x, tid = threadIdx.x;
    float e[4];
#pragma unroll
    for (int i = 0; i < 4; i++) {
        const int s = tid + i * 256;
        float v = 0.f;
#pragma unroll
        for (int nt = 0; nt < 8; nt++) v += g_epart[(size_t)nt * 65536 + b * 1024 + s];
        e[i] = v;
    }
    float mx = fmaxf(fmaxf(e[0], e[1]), fmaxf(e[2], e[3]));
#pragma unroll
    for (int off = 16; off; off >>= 1) mx = fmaxf(mx, __shfl_xor_sync(0xffffffffu, mx, off));
    if ((tid & 31) == 0) red[tid >> 5] = mx;
    __syncthreads();
    if (tid < 32) {
        float m = (tid < 8) ? red[tid] : -1e30f;
#pragma unroll
        for (int off = 4; off; off >>= 1) m = fmaxf(m, __shfl_xor_sync(0xffffffffu, m, off));
        red[tid] = m;
    }
    __syncthreads();
    mx = red[0];
    __syncthreads();

    float ex[4], sum = 0.f;
#pragma unroll
    for (int i = 0; i < 4; i++) { ex[i] = __expf(e[i] - mx); sum += ex[i]; }
#pragma unroll
    for (int off = 16; off; off >>= 1) sum += __shfl_xor_sync(0xffffffffu, sum, off);
    if ((tid & 31) == 0) red[tid >> 5] = sum;
    __syncthreads();
    if (tid < 32) {
        float s = (tid < 8) ? red[tid] : 0.f;
#pragma unroll
        for (int off = 4; off; off >>= 1) s += __shfl_xor_sync(0xffffffffu, s, off);
        red[tid] = s;
    }
    __syncthreads();
    const float inv = 1.f / red[0];
#pragma unroll
    for (int i = 0; i < 4; i++) {
        const int s = tid + i * 256;
        const float sc = ex[i] * inv;
        out[65536 + b * 1024 + s]  = sc;                       // score
        out[131072 + b * 1024 + s] = cov[b * 1024 + s] + sc;   // coverage_new
    }
}

// =====================================================================
// k4: weightedContext[b][a] = sum_s score[b][s] * context[b][s][a]
// grid (64 b, 8 chunks of 128 floats), 128 threads, 4-way split-K
// =====================================================================
__global__ void __launch_bounds__(128) k4_wctx(
    const float* __restrict__ ctx, const float* __restrict__ score,
    float* __restrict__ out)
{
    __shared__ float sc[1024];
    __shared__ float4 part[4][32];
    const int b = blockIdx.x, chunk = blockIdx.y, tid = threadIdx.x;
    for (int i = tid; i < 1024; i += 128) sc[i] = score[b * 1024 + i];
    __syncthreads();
    const int c32 = tid & 31;                     // float4 column within chunk
    const int ks = tid >> 5;                      // k-slice 0..3
    const int a4 = chunk * 32 + c32;
    const float4* cp = (const float4*)(ctx + (size_t)b * 1048576) + a4;
    float4 acc = make_float4(0.f, 0.f, 0.f, 0.f);
    const int s_begin = ks * 256, s_end = s_begin + 256;
    for (int s0 = s_begin; s0 < s_end; s0 += 8) {
        float4 v[8];
#pragma unroll
        for (int u = 0; u < 8; u++) v[u] = cp[(size_t)(s0 + u) * 256];
#pragma unroll
        for (int u = 0; u < 8; u++) {
            const float s = sc[s0 + u];
            acc.x += s * v[u].x; acc.y += s * v[u].y;
            acc.z += s * v[u].z; acc.w += s * v[u].w;
        }
    }
    part[ks][c32] = acc;
    __syncthreads();
    if (ks == 0) {
        float4 p1 = part[1][c32], p2 = part[2][c32], p3 = part[3][c32];
        acc.x += p1.x + p2.x + p3.x;
        acc.y += p1.y + p2.y + p3.y;
        acc.z += p1.z + p2.z + p3.z;
        acc.w += p1.w + p2.w + p3.w;
        ((float4*)out)[b * 256 + a4] = acc;
    }
}

// =====================================================================
extern "C" void kernel_launch(void* const* d_in, const int* in_sizes, int n_in,
                              void* d_out, int out_size) {
    const float* input   = (const float*)d_in[0];
    const float* context = (const float*)d_in[1];
    const float* cov     = (const float*)d_in[2];
    const float* Wpre    = (const float*)d_in[3];
    const float* bpre    = (const float*)d_in[4];
    const float* Wq      = (const float*)d_in[5];
    const float* Wv      = (const float*)d_in[6];
    const float* Wcov    = (const float*)d_in[7];
    float* out = (float*)d_out;
    // layout: weightedContext (65536) | score (65536) | coverage_new (65536)
    //         | precompute (67108864)

    cudaFuncSetAttribute(k2_gemm, cudaFuncAttributeMaxDynamicSharedMemorySize, K2_SMEM);

    k0_ctx<<<2048, 256>>>((const float4*)context);
    k0_wpre<<<256, 256>>>((const float4*)Wpre);

    dim3 g1(8, 8);
    k1_target<<<g1, 256>>>(input, Wq);

    dim3 g2(8, 512);
    k2_gemm<<<g2, 128, K2_SMEM>>>(bpre, cov, Wv, Wcov, out + 196608);

    k3_softmax<<<64, 256>>>(cov, out);

    dim3 g4(64, 8);
    k4_wctx<<<g4, 128>>>(context, out + 65536, out);
}

// round 6
// speedup vs baseline: 1.3261x; 1.0953x over previous
#include <cuda_runtime.h>
#include <cuda_fp16.h>
#include <cstdint>

// ---------------- device scratch (allocations are forbidden) ----------------
__device__ float g_target[64 * 1024];          // input @ W_q^T  (B, D)
__device__ float g_epart[8 * 64 * 1024];       // per-d-tile energy partials (8, B*S)
__device__ __half g_ctx_h[64 * 1024 * 1024];   // fp16 context (128 MB)
__device__ __half g_wpre_h[1024 * 1024];       // fp16 W_pre (2 MB)

// ---------------- helpers ----------------
__device__ __forceinline__ uint32_t smem_u32(const void* p) {
    uint32_t a;
    asm("{ .reg .u64 t; cvta.to.shared.u64 t, %1; cvt.u32.u64 %0, t; }" : "=r"(a) : "l"(p));
    return a;
}
__device__ __forceinline__ void cp_async16(uint32_t dst, const void* src) {
    asm volatile("cp.async.cg.shared.global [%0], [%1], 16;" :: "r"(dst), "l"(src));
}
__device__ __forceinline__ void cp_commit() { asm volatile("cp.async.commit_group;" ::: "memory"); }
template<int N> __device__ __forceinline__ void cp_wait() {
    asm volatile("cp.async.wait_group %0;" :: "n"(N) : "memory");
}
__device__ __forceinline__ float tanh_fast(float x) {
    float y;
    asm("tanh.approx.f32 %0, %1;" : "=f"(y) : "f"(x));
    return y;
}
__device__ __forceinline__ void ldsm4(uint32_t& r0, uint32_t& r1, uint32_t& r2,
                                      uint32_t& r3, uint32_t addr) {
    asm volatile("ldmatrix.sync.aligned.m8n8.x4.shared.b16 {%0,%1,%2,%3}, [%4];"
                 : "=r"(r0), "=r"(r1), "=r"(r2), "=r"(r3) : "r"(addr));
}
__device__ __forceinline__ void mma_f16(float* d, const uint32_t* a, uint32_t b0, uint32_t b1) {
    asm volatile(
        "mma.sync.aligned.m16n8k16.row.col.f32.f16.f16.f32 "
        "{%0,%1,%2,%3}, {%4,%5,%6,%7}, {%8,%9}, {%0,%1,%2,%3};"
        : "+f"(d[0]), "+f"(d[1]), "+f"(d[2]), "+f"(d[3])
        : "r"(a[0]), "r"(a[1]), "r"(a[2]), "r"(a[3]), "r"(b0), "r"(b1));
}

// =====================================================================
// k0: f32 -> fp16 conversion (context / W_pre) into device globals
// =====================================================================
__global__ void k0_ctx(const float4* __restrict__ src) {
    uint2* dst = reinterpret_cast<uint2*>(g_ctx_h);
    const int stride = gridDim.x * blockDim.x;
    for (int i = blockIdx.x * blockDim.x + threadIdx.x; i < 16777216; i += stride) {
        float4 v = src[i];
        __half2 h0 = __float22half2_rn(make_float2(v.x, v.y));
        __half2 h1 = __float22half2_rn(make_float2(v.z, v.w));
        uint2 o;
        o.x = *reinterpret_cast<uint32_t*>(&h0);
        o.y = *reinterpret_cast<uint32_t*>(&h1);
        dst[i] = o;
    }
}
__global__ void k0_wpre(const float4* __restrict__ src) {
    uint2* dst = reinterpret_cast<uint2*>(g_wpre_h);
    const int stride = gridDim.x * blockDim.x;
    for (int i = blockIdx.x * blockDim.x + threadIdx.x; i < 262144; i += stride) {
        float4 v = src[i];
        __half2 h0 = __float22half2_rn(make_float2(v.x, v.y));
        __half2 h1 = __float22half2_rn(make_float2(v.z, v.w));
        uint2 o;
        o.x = *reinterpret_cast<uint32_t*>(&h0);
        o.y = *reinterpret_cast<uint32_t*>(&h1);
        dst[i] = o;
    }
}

// =====================================================================
// k1: target[b][d] = sum_a input[b][a] * W_q[d][a]   (fp32 exact)
// =====================================================================
__global__ void k1_target(const float* __restrict__ inp, const float* __restrict__ Wq) {
    __shared__ float insh[8][1024];
    const int dt = blockIdx.x, bg = blockIdx.y, tid = threadIdx.x;
    for (int i = tid; i < 8192; i += 256)
        insh[i >> 10][i & 1023] = inp[(bg * 8 + (i >> 10)) * 1024 + (i & 1023)];
    __syncthreads();
    const int w = tid >> 5, l = tid & 31;
    for (int j = 0; j < 16; j++) {
        const int d = dt * 128 + w * 16 + j;
        const float* wr = Wq + (size_t)d * 1024;
        float acc[8] = {0.f, 0.f, 0.f, 0.f, 0.f, 0.f, 0.f, 0.f};
        for (int a = l; a < 1024; a += 32) {
            const float wv = wr[a];
#pragma unroll
            for (int bb = 0; bb < 8; bb++) acc[bb] += wv * insh[bb][a];
        }
#pragma unroll
        for (int bb = 0; bb < 8; bb++) {
            float v = acc[bb];
#pragma unroll
            for (int off = 16; off; off >>= 1) v += __shfl_xor_sync(0xffffffffu, v, off);
            if (l == 0) g_target[(bg * 8 + bb) * 1024 + d] = v;
        }
    }
}

// =====================================================================
// k2: fp16 m16n8k16 GEMM + fused tanh/energy epilogue
//   CTA 128(M) x 128(N), 256 threads (8 warps as 2m x 4n, warp 64x32),
//   K=1024 in 64 chunks of 16, 4-stage cp.async ring, ONE barrier/iter.
// =====================================================================
constexpr int K2_STAGE   = 8192;    // A 4KB + B 4KB
constexpr int K2_VEC_OFF = 32768;   // 4 x 128 floats
constexpr int K2_ESH_OFF = 34816;   // 128 x 4 floats
constexpr int K2_SMEM    = 36864;

__global__ void __launch_bounds__(256, 2) k2_gemm(
    const float* __restrict__ bpre, const float* __restrict__ cov,
    const float* __restrict__ Wv, const float* __restrict__ Wcov,
    float* __restrict__ outPre)
{
    extern __shared__ char smem[];
    const uint32_t sb = smem_u32(smem);
    float* vecs = (float*)(smem + K2_VEC_OFF);
    float (*e_sh)[4] = (float (*)[4])(smem + K2_ESH_OFF);

    const int nt = blockIdx.x;                 // 0..7   (128-wide d tile)
    const int mt = blockIdx.y;                 // 0..511 (128-row tile)
    const int tid = threadIdx.x;
    const int lane = tid & 31, warp = tid >> 5;
    const int wm = (warp & 1) * 64, wn = (warp >> 1) * 32;
    const int d0 = nt * 128;
    const size_t row0 = (size_t)mt * 128;
    const int b = mt >> 3;

    if (tid < 128) {
        vecs[tid]       = bpre[d0 + tid];
        vecs[128 + tid] = g_target[b * 1024 + d0 + tid];
        vecs[256 + tid] = Wv[d0 + tid];
        vecs[384 + tid] = Wcov[d0 + tid];
    }

    // ----- per-thread cp.async setup (threads 0-127: A rows, 128-255: B rows)
    const int lrow = tid & 127;
    const __half* gsrc = (tid < 128)
        ? g_ctx_h + (row0 + lrow) * 1024
        : g_wpre_h + (size_t)(d0 + lrow) * 1024;
    const uint32_t swz = ((lrow >> 2) & 1) << 4;
    const uint32_t dbase = sb + ((tid < 128) ? 0u : 4096u) + lrow * 32;
    const uint32_t dst0 = dbase + swz;
    const uint32_t dst1 = dbase + (swz ^ 16);

    // ----- per-lane ldmatrix addresses (constant across kt)
    const int sub = lane >> 3, idx = lane & 7;
    const int rit = (sub & 1) * 8 + idx;
    const int kseg = sub >> 1;
    uint32_t offA[4], offB[2];
#pragma unroll
    for (int t = 0; t < 4; t++) {
        const int rA = wm + t * 16 + rit;
        offA[t] = (uint32_t)(rA * 32 + ((kseg ^ ((rA >> 2) & 1)) << 4));
    }
#pragma unroll
    for (int t = 0; t < 2; t++) {
        const int rB = wn + t * 16 + rit;
        offB[t] = (uint32_t)(4096 + rB * 32 + ((kseg ^ ((rB >> 2) & 1)) << 4));
    }

    float acc[4][4][4];
#pragma unroll
    for (int i = 0; i < 4; i++)
#pragma unroll
        for (int j = 0; j < 4; j++)
#pragma unroll
            for (int r = 0; r < 4; r++) acc[i][j][r] = 0.f;

    // prologue: stages 0..2
#pragma unroll
    for (int p = 0; p < 3; p++) {
        cp_async16(dst0 + p * K2_STAGE, gsrc + p * 16);
        cp_async16(dst1 + p * K2_STAGE, gsrc + p * 16 + 8);
        cp_commit();
    }

    for (int kt = 0; kt < 64; kt++) {
        if (kt < 61) cp_wait<2>();
        else if (kt == 61) cp_wait<1>();
        else if (kt == 62) cp_wait<0>();
        __syncthreads();

        if (kt + 3 < 64) {
            const uint32_t so = ((kt + 3) & 3) * K2_STAGE;
            cp_async16(dst0 + so, gsrc + (kt + 3) * 16);
            cp_async16(dst1 + so, gsrc + (kt + 3) * 16 + 8);
            cp_commit();
        }

        const uint32_t stb = sb + (kt & 3) * K2_STAGE;
        uint32_t a[4][4], bq[2][4];
#pragma unroll
        for (int tm = 0; tm < 4; tm++)
            ldsm4(a[tm][0], a[tm][1], a[tm][2], a[tm][3], stb + offA[tm]);
#pragma unroll
        for (int tp = 0; tp < 2; tp++)
            ldsm4(bq[tp][0], bq[tp][1], bq[tp][2], bq[tp][3], stb + offB[tp]);
#pragma unroll
        for (int tm = 0; tm < 4; tm++)
#pragma unroll
            for (int tn = 0; tn < 4; tn++)
                mma_f16(acc[tm][tn], a[tm],
                        bq[tn >> 1][tn & 1], bq[tn >> 1][2 + (tn & 1)]);
    }

    // ---------------- epilogue: bias + precompute + tanh/energy ----------------
    const int g = lane >> 2, t4 = lane & 3;
    const float* bias_sh = vecs;
    const float* tgt_sh  = vecs + 128;
    const float* wv_sh   = vecs + 256;
    const float* wcov_sh = vecs + 384;

#pragma unroll
    for (int tm = 0; tm < 4; tm++) {
#pragma unroll
        for (int h = 0; h < 2; h++) {
            const int rowL = wm + tm * 16 + h * 8 + g;
            const size_t grow = row0 + rowL;
            const float cv = cov[grow];
            float* orow = outPre + grow * 1024 + d0;
            float e = 0.f;
#pragma unroll
            for (int tn = 0; tn < 4; tn++) {
                const int colL = wn + tn * 8 + 2 * t4;
                const float v0 = acc[tm][tn][h * 2 + 0] + bias_sh[colL];
                const float v1 = acc[tm][tn][h * 2 + 1] + bias_sh[colL + 1];
                *reinterpret_cast<float2*>(orow + colL) = make_float2(v0, v1);
                e += tanh_fast(v0 + tgt_sh[colL]     + cv * wcov_sh[colL])     * wv_sh[colL];
                e += tanh_fast(v1 + tgt_sh[colL + 1] + cv * wcov_sh[colL + 1]) * wv_sh[colL + 1];
            }
            e += __shfl_xor_sync(0xffffffffu, e, 1);
            e += __shfl_xor_sync(0xffffffffu, e, 2);
            if (t4 == 0) e_sh[rowL][warp >> 1] = e;
        }
    }
    __syncthreads();
    if (tid < 128)
        g_epart[(size_t)nt * 65536 + row0 + tid] =
            (e_sh[tid][0] + e_sh[tid][1]) + (e_sh[tid][2] + e_sh[tid][3]);
}

// =====================================================================
// k3: energy reduce + softmax + coverage. One block per b, 256 threads.
// =====================================================================
__global__ void k3_softmax(const float* __restrict__ cov, float* __restrict__ out) {
    __shared__ float red[32];
    const int b = blockIdx.x, tid = threadIdx.x;
    float e[4];
#pragma unroll
    for (int i = 0; i < 4; i++) {
        const int s = tid + i * 256;
        float v = 0.f;
#pragma unroll
        for (int nt = 0; nt < 8; nt++) v += g_epart[(size_t)nt * 65536 + b * 1024 + s];
        e[i] = v;
    }
    float mx = fmaxf(fmaxf(e[0], e[1]), fmaxf(e[2], e[3]));
#pragma unroll
    for (int off = 16; off; off >>= 1) mx = fmaxf(mx, __shfl_xor_sync(0xffffffffu, mx, off));
    if ((tid & 31) == 0) red[tid >> 5] = mx;
    __syncthreads();
    if (tid < 32) {
        float m = (tid < 8) ? red[tid] : -1e30f;
#pragma unroll
        for (int off = 4; off; off >>= 1) m = fmaxf(m, __shfl_xor_sync(0xffffffffu, m, off));
        red[tid] = m;
    }
    __syncthreads();
    mx = red[0];
    __syncthreads();

    float ex[4], sum = 0.f;
#pragma unroll
    for (int i = 0; i < 4; i++) { ex[i] = __expf(e[i] - mx); sum += ex[i]; }
#pragma unroll
    for (int off = 16; off; off >>= 1) sum += __shfl_xor_sync(0xffffffffu, sum, off);
    if ((tid & 31) == 0) red[tid >> 5] = sum;
    __syncthreads();
    if (tid < 32) {
        float s = (tid < 8) ? red[tid] : 0.f;
#pragma unroll
        for (int off = 4; off; off >>= 1) s += __shfl_xor_sync(0xffffffffu, s, off);
        red[tid] = s;
    }
    __syncthreads();
    const float inv = 1.f / red[0];
#pragma unroll
    for (int i = 0; i < 4; i++) {
        const int s = tid + i * 256;
        const float sc = ex[i] * inv;
        out[65536 + b * 1024 + s]  = sc;                       // score
        out[131072 + b * 1024 + s] = cov[b * 1024 + s] + sc;   // coverage_new
    }
}

// =====================================================================
// k4: weightedContext[b][a] = sum_s score[b][s] * context[b][s][a]
// grid (64 b, 8 chunks of 128 floats), 128 threads, 4-way split-K
// =====================================================================
__global__ void __launch_bounds__(128) k4_wctx(
    const float* __restrict__ ctx, const float* __restrict__ score,
    float* __restrict__ out)
{
    __shared__ float sc[1024];
    __shared__ float4 part[4][32];
    const int b = blockIdx.x, chunk = blockIdx.y, tid = threadIdx.x;
    for (int i = tid; i < 1024; i += 128) sc[i] = score[b * 1024 + i];
    __syncthreads();
    const int c32 = tid & 31;
    const int ks = tid >> 5;
    const int a4 = chunk * 32 + c32;
    const float4* cp = (const float4*)(ctx + (size_t)b * 1048576) + a4;
    float4 acc = make_float4(0.f, 0.f, 0.f, 0.f);
    const int s_begin = ks * 256, s_end = s_begin + 256;
    for (int s0 = s_begin; s0 < s_end; s0 += 8) {
        float4 v[8];
#pragma unroll
        for (int u = 0; u < 8; u++) v[u] = cp[(size_t)(s0 + u) * 256];
#pragma unroll
        for (int u = 0; u < 8; u++) {
            const float s = sc[s0 + u];
            acc.x += s * v[u].x; acc.y += s * v[u].y;
            acc.z += s * v[u].z; acc.w += s * v[u].w;
        }
    }
    part[ks][c32] = acc;
    __syncthreads();
    if (ks == 0) {
        float4 p1 = part[1][c32], p2 = part[2][c32], p3 = part[3][c32];
        acc.x += p1.x + p2.x + p3.x;
        acc.y += p1.y + p2.y + p3.y;
        acc.z += p1.z + p2.z + p3.z;
        acc.w += p1.w + p2.w + p3.w;
        ((float4*)out)[b * 256 + a4] = acc;
    }
}

// =====================================================================
extern "C" void kernel_launch(void* const* d_in, const int* in_sizes, int n_in,
                              void* d_out, int out_size) {
    const float* input   = (const float*)d_in[0];
    const float* context = (const float*)d_in[1];
    const float* cov     = (const float*)d_in[2];
    const float* Wpre    = (const float*)d_in[3];
    const float* bpre    = (const float*)d_in[4];
    const float* Wq      = (const float*)d_in[5];
    const float* Wv      = (const float*)d_in[6];
    const float* Wcov    = (const float*)d_in[7];
    float* out = (float*)d_out;
    // layout: weightedContext (65536) | score (65536) | coverage_new (65536)
    //         | precompute (67108864)

    cudaFuncSetAttribute(k2_gemm, cudaFuncAttributeMaxDynamicSharedMemorySize, K2_SMEM);

    k0_ctx<<<2048, 256>>>((const float4*)context);
    k0_wpre<<<256, 256>>>((const float4*)Wpre);

    dim3 g1(8, 8);
    k1_target<<<g1, 256>>>(input, Wq);

    dim3 g2(8, 512);
    k2_gemm<<<g2, 256, K2_SMEM>>>(bpre, cov, Wv, Wcov, out + 196608);

    k3_softmax<<<64, 256>>>(cov, out);

    dim3 g4(64, 8);
    k4_wctx<<<g4, 128>>>(context, out + 65536, out);
}